// round 1
// baseline (speedup 1.0000x reference)
#include <cuda_runtime.h>
#include <cuda_bf16.h>

#define BQ 4
#define TQ 2048
#define DQ 1024
#define HQ 16
#define SQ 64
#define CQ 64
#define MROWS (BQ*TQ)   /* 8192 */

// ---------------- device scratch (sanctioned workaround for no-malloc rule) ----
__device__ __nv_bfloat16 g_wq[5u*1024u*1024u];      // ternary weights (bf16 exact)
__device__ float         g_wscale[5];
__device__ __nv_bfloat16 g_xq[4u*MROWS*DQ];         // quantized activations r,k,v,g
__device__ float         g_xscale[4*MROWS];
__device__ float         g_r[MROWS*DQ];             // (B,H,T,S)
__device__ float         g_k[MROWS*DQ];
__device__ float         g_v[MROWS*DQ];
__device__ float         g_gate[MROWS*DQ];          // (B,T,D)
__device__ float         g_y[MROWS*DQ];             // wkv out (B,H,T,S)
__device__ __nv_bfloat16 g_xq5[MROWS*DQ];
__device__ float         g_xscale5[MROWS];

// ---------------- helpers -----------------------------------------------------
__device__ __forceinline__ float blockReduce256(float v, float* sh) {
    #pragma unroll
    for (int o = 16; o; o >>= 1) v += __shfl_xor_sync(0xffffffffu, v, o);
    __syncthreads();
    if ((threadIdx.x & 31) == 0) sh[threadIdx.x >> 5] = v;
    __syncthreads();
    if (threadIdx.x == 0) { float s = sh[0]; for (int i = 1; i < 8; i++) s += sh[i]; sh[0] = s; }
    __syncthreads();
    return sh[0];
}

__device__ __forceinline__ void mma_bf16(float c[4], const unsigned a[4], const unsigned b[2]) {
    asm volatile(
        "mma.sync.aligned.m16n8k16.row.col.f32.bf16.bf16.f32 "
        "{%0,%1,%2,%3}, {%4,%5,%6,%7}, {%8,%9}, {%0,%1,%2,%3};\n"
        : "+f"(c[0]), "+f"(c[1]), "+f"(c[2]), "+f"(c[3])
        : "r"(a[0]), "r"(a[1]), "r"(a[2]), "r"(a[3]), "r"(b[0]), "r"(b[1]));
}

// ---------------- weight quantization -----------------------------------------
__global__ void wq_scale_kernel(const float* __restrict__ w) {
    __shared__ float sh[32];
    int z = blockIdx.x;
    const float* wz = w + (size_t)z * 1024u * 1024u;
    float s = 0.f;
    for (int j = threadIdx.x; j < 1024 * 1024; j += 1024) s += fabsf(wz[j]);
    #pragma unroll
    for (int o = 16; o; o >>= 1) s += __shfl_xor_sync(0xffffffffu, s, o);
    if ((threadIdx.x & 31) == 0) sh[threadIdx.x >> 5] = s;
    __syncthreads();
    if (threadIdx.x == 0) {
        float t = 0.f; for (int i = 0; i < 32; i++) t += sh[i];
        g_wscale[z] = fmaxf(t * (1.f / 1048576.f), 1e-8f);
    }
}

__global__ void wq_quant_kernel(const float* __restrict__ w) {
    int idx = (blockIdx.x * 256 + threadIdx.x) * 4;
    int z = idx >> 20;
    float s = g_wscale[z];
    float4 wv = *(const float4*)(w + idx);
    float vv[4] = {wv.x, wv.y, wv.z, wv.w};
    __nv_bfloat16 q[4];
    #pragma unroll
    for (int j = 0; j < 4; j++) {
        float wn = vv[j] / s;
        wn = fminf(fmaxf(wn, -1.f), 1.f);
        q[j] = __float2bfloat16(rintf(wn));
    }
    *(__nv_bfloat162*)(g_wq + idx)     = __nv_bfloat162(q[0], q[1]);
    *(__nv_bfloat162*)(g_wq + idx + 2) = __nv_bfloat162(q[2], q[3]);
}

// ---------------- token shift + LN + act quant for r,k,v,g --------------------
__global__ void lnq4_kernel(const float* __restrict__ x,
                            const float* __restrict__ mu_r, const float* __restrict__ mu_k,
                            const float* __restrict__ mu_v, const float* __restrict__ mu_g,
                            const float* __restrict__ ln_g, const float* __restrict__ ln_b) {
    __shared__ float sh[16];
    int m = blockIdx.x;
    int d0 = threadIdx.x * 4;
    const float* xr = x + (size_t)m * DQ;
    float4 xv = *(const float4*)(xr + d0);
    float4 xsv = make_float4(0.f, 0.f, 0.f, 0.f);
    if ((m & (TQ - 1)) != 0) xsv = *(const float4*)(xr - DQ + d0);
    float xb[4] = {xv.x, xv.y, xv.z, xv.w};
    float dx[4] = {xsv.x - xv.x, xsv.y - xv.y, xsv.z - xv.z, xsv.w - xv.w};
    const float* mus[4] = {mu_r, mu_k, mu_v, mu_g};
    #pragma unroll
    for (int i = 0; i < 4; i++) {
        float4 mu = *(const float4*)(mus[i] + d0);
        float mm[4] = {mu.x, mu.y, mu.z, mu.w};
        float inp[4];
        float s = 0.f;
        #pragma unroll
        for (int j = 0; j < 4; j++) { inp[j] = fmaf(dx[j], mm[j], xb[j]); s += inp[j]; }
        float mean = blockReduce256(s, sh) * (1.f / DQ);
        float s2 = 0.f;
        #pragma unroll
        for (int j = 0; j < 4; j++) { float c = inp[j] - mean; s2 += c * c; }
        float var = blockReduce256(s2, sh) * (1.f / DQ);
        float rstd = rsqrtf(var + 1e-5f);
        float xl[4]; float sa = 0.f;
        #pragma unroll
        for (int j = 0; j < 4; j++) {
            float v = (inp[j] - mean) * rstd * ln_g[i * DQ + d0 + j] + ln_b[i * DQ + d0 + j];
            xl[j] = v; sa += fabsf(v);
        }
        float ma = blockReduce256(sa, sh) * (1.f / DQ);
        float clipv = fmaxf(ma, 1e-8f) * 2.5f;
        float scale = clipv / 127.f;
        __nv_bfloat16 q[4];
        #pragma unroll
        for (int j = 0; j < 4; j++)
            q[j] = __float2bfloat16(rintf(fminf(fmaxf(xl[j] / scale, -127.f), 127.f)));
        size_t off = (size_t)i * MROWS * DQ + (size_t)m * DQ + d0;
        *(__nv_bfloat162*)(g_xq + off)     = __nv_bfloat162(q[0], q[1]);
        *(__nv_bfloat162*)(g_xq + off + 2) = __nv_bfloat162(q[2], q[3]);
        if (threadIdx.x == 0) g_xscale[i * MROWS + m] = scale;
    }
}

// ---------------- bf16 tensor-core GEMM: out = scale * (Xq @ Wq^T) ------------
// A: [8192,1024] K-major; B(=Wq): [1024,1024] K-major; block tile 128x128, BK=32.
__global__ void __launch_bounds__(256) gemm_kernel(float* __restrict__ out_final) {
    __shared__ __nv_bfloat16 As[128][40];
    __shared__ __nv_bfloat16 Bs[128][40];
    int proj = (gridDim.z > 1) ? blockIdx.z : 4;
    const __nv_bfloat16* Ag = (proj < 4) ? (g_xq + (size_t)proj * MROWS * DQ) : g_xq5;
    const __nv_bfloat16* Bg = g_wq + (size_t)proj * DQ * DQ;
    int bm = blockIdx.x, bn = blockIdx.y;
    int tid = threadIdx.x;
    int warp = tid >> 5, lane = tid & 31, g = lane >> 2, tig = lane & 3;
    int wm = warp >> 1, wn = warp & 1;  // 4x2 warp grid; warp tile 32x64
    float acc[2][8][4];
    #pragma unroll
    for (int a = 0; a < 2; a++)
        #pragma unroll
        for (int b = 0; b < 8; b++)
            #pragma unroll
            for (int cidx = 0; cidx < 4; cidx++) acc[a][b][cidx] = 0.f;

    const __nv_bfloat16* Abase = Ag + (size_t)(bm * 128) * DQ;
    const __nv_bfloat16* Bbase = Bg + (size_t)(bn * 128) * DQ;

    for (int kt = 0; kt < DQ; kt += 32) {
        #pragma unroll
        for (int hh = 0; hh < 2; hh++) {
            int c = tid + hh * 256;
            int row = c >> 2, cc = c & 3;
            *(uint4*)&As[row][cc * 8] = *(const uint4*)(Abase + (size_t)row * DQ + kt + cc * 8);
            *(uint4*)&Bs[row][cc * 8] = *(const uint4*)(Bbase + (size_t)row * DQ + kt + cc * 8);
        }
        __syncthreads();
        #pragma unroll
        for (int ks = 0; ks < 2; ks++) {
            int kc = ks * 16 + tig * 2;
            unsigned af[2][4], bf[8][2];
            #pragma unroll
            for (int mt = 0; mt < 2; mt++) {
                int row = wm * 32 + mt * 16 + g;
                af[mt][0] = *(const unsigned*)&As[row][kc];
                af[mt][1] = *(const unsigned*)&As[row + 8][kc];
                af[mt][2] = *(const unsigned*)&As[row][kc + 8];
                af[mt][3] = *(const unsigned*)&As[row + 8][kc + 8];
            }
            #pragma unroll
            for (int nt = 0; nt < 8; nt++) {
                int rowb = wn * 64 + nt * 8 + g;
                bf[nt][0] = *(const unsigned*)&Bs[rowb][kc];
                bf[nt][1] = *(const unsigned*)&Bs[rowb][kc + 8];
            }
            #pragma unroll
            for (int mt = 0; mt < 2; mt++)
                #pragma unroll
                for (int nt = 0; nt < 8; nt++)
                    mma_bf16(acc[mt][nt], af[mt], bf[nt]);
        }
        __syncthreads();
    }

    float sw = g_wscale[proj];
    #pragma unroll
    for (int mt = 0; mt < 2; mt++) {
        int mrow0 = bm * 128 + wm * 32 + mt * 16 + g;
        float sx0 = ((proj < 4) ? g_xscale[proj * MROWS + mrow0]     : g_xscale5[mrow0])     * sw;
        float sx1 = ((proj < 4) ? g_xscale[proj * MROWS + mrow0 + 8] : g_xscale5[mrow0 + 8]) * sw;
        #pragma unroll
        for (int nt = 0; nt < 8; nt++) {
            #pragma unroll
            for (int idx = 0; idx < 4; idx++) {
                int mrow = mrow0 + (idx >> 1) * 8;
                int ncol = bn * 128 + wn * 64 + nt * 8 + tig * 2 + (idx & 1);
                float val = acc[mt][nt][idx] * ((idx >= 2) ? sx1 : sx0);
                if (proj == 4) {
                    out_final[(size_t)mrow * DQ + ncol] = val;
                } else if (proj == 3) {
                    g_gate[(size_t)mrow * DQ + ncol] = val;
                } else {
                    float* dst = (proj == 0) ? g_r : (proj == 1) ? g_k : g_v;
                    int bb = mrow >> 11, tt = mrow & (TQ - 1);
                    int hh = ncol >> 6, ss = ncol & 63;
                    dst[(((size_t)(bb * HQ + hh) * TQ) + tt) * SQ + ss] = val;
                }
            }
        }
    }
}

// ---------------- WKV recurrence ----------------------------------------------
// Per chunk (anti-causal intra-chunk per reference):
//   backward t: Q_t = kv_t + w*Q_{t+1};  y_t = sum_s r_t (Q_t + u_exp*kv_t + w^{t+1}*S)
//   R = sum_t w^{C-1-t} kv_t;  S <- w^C * S + R
__global__ void wkv_kernel(const float* __restrict__ log_decay, const float* __restrict__ uu) {
    __shared__ float rs[4096], ksm[4096], wp[4096];   // 48 KB exactly
    int bh = blockIdx.x >> 3;
    int og = blockIdx.x & 7;
    int h = bh & (HQ - 1);
    int tid = threadIdx.x, warp = tid >> 5, lane = tid & 31;
    int o = og * 8 + warp;
    int s0 = lane, s1 = lane + 32;

    #pragma unroll
    for (int j = 0; j < 16; j++) {
        int e = tid + j * 256;
        int tt = e >> 6, ss = e & 63;
        float lw = -expf(log_decay[h * 64 + ss]);          // log(w)
        wp[e] = expf((float)(tt + 1) * lw);                // w^{t+1}, t=0..63
    }
    __syncthreads();
    float w0 = wp[s0], w1 = wp[s1];
    float wC0 = wp[63 * 64 + s0], wC1 = wp[63 * 64 + s1];
    float u0 = expf(uu[h * 64 + s0]), u1 = expf(uu[h * 64 + s1]);
    float S0 = 0.f, S1 = 0.f;
    size_t bhbase = (size_t)bh * TQ * SQ;

    for (int c = 0; c < TQ / CQ; c++) {
        size_t base = bhbase + (size_t)c * CQ * SQ;
        #pragma unroll
        for (int j = 0; j < 16; j++) {
            int e = tid + j * 256;
            rs[e] = g_r[base + e];
            ksm[e] = g_k[base + e];
        }
        float vlo = g_v[base + (size_t)lane * SQ + o];
        float vhi = g_v[base + (size_t)(lane + 32) * SQ + o];
        __syncthreads();
        float Q0 = 0.f, Q1 = 0.f, R0 = 0.f, R1 = 0.f, pw0 = 1.f, pw1 = 1.f;
        for (int t = CQ - 1; t >= 0; t--) {
            float vt = __shfl_sync(0xffffffffu, (t < 32) ? vlo : vhi, t & 31);
            float k0 = ksm[t * 64 + s0], k1 = ksm[t * 64 + s1];
            float r0 = rs[t * 64 + s0],  r1 = rs[t * 64 + s1];
            float wpt0 = wp[t * 64 + s0], wpt1 = wp[t * 64 + s1];
            float kv0 = k0 * vt, kv1 = k1 * vt;
            Q0 = fmaf(w0, Q0, kv0); Q1 = fmaf(w1, Q1, kv1);
            float a0 = Q0 + u0 * kv0 + wpt0 * S0;
            float a1 = Q1 + u1 * kv1 + wpt1 * S1;
            float p = r0 * a0 + r1 * a1;
            R0 = fmaf(pw0, kv0, R0); R1 = fmaf(pw1, kv1, R1);
            pw0 *= w0; pw1 *= w1;
            #pragma unroll
            for (int off = 16; off; off >>= 1) p += __shfl_xor_sync(0xffffffffu, p, off);
            if (lane == 0) g_y[base + (size_t)t * SQ + o] = p;
        }
        S0 = fmaf(wC0, S0, R0); S1 = fmaf(wC1, S1, R1);
        __syncthreads();
    }
}

// ---------------- GroupNorm + SiLU gate + LN + quant (proj 4 input) -----------
__global__ void gngate_kernel(const float* __restrict__ gn_g, const float* __restrict__ gn_b,
                              const float* __restrict__ ln_g, const float* __restrict__ ln_b) {
    __shared__ float sh[16];
    int m = blockIdx.x;
    int b = m >> 11, t = m & (TQ - 1);
    int d0 = threadIdx.x * 4;
    int h = d0 >> 6, s = d0 & 63;
    float4 yv4 = *(const float4*)(g_y + ((size_t)(b * HQ + h) * TQ + t) * SQ + s);
    float yv[4] = {yv4.x, yv4.y, yv4.z, yv4.w};
    float gs = yv[0] + yv[1] + yv[2] + yv[3];
    #pragma unroll
    for (int off = 8; off; off >>= 1) gs += __shfl_xor_sync(0xffffffffu, gs, off);
    float gm = gs * (1.f / 64.f);
    float g2 = 0.f;
    #pragma unroll
    for (int j = 0; j < 4; j++) { float c = yv[j] - gm; g2 += c * c; }
    #pragma unroll
    for (int off = 8; off; off >>= 1) g2 += __shfl_xor_sync(0xffffffffu, g2, off);
    float rstd = rsqrtf(g2 * (1.f / 64.f) + 1e-5f);
    float4 gg4 = *(const float4*)(g_gate + (size_t)m * DQ + d0);
    float gg[4] = {gg4.x, gg4.y, gg4.z, gg4.w};
    float val[4];
    float ssum = 0.f;
    #pragma unroll
    for (int j = 0; j < 4; j++) {
        float yn = (yv[j] - gm) * rstd * gn_g[d0 + j] + gn_b[d0 + j];
        float gv = gg[j];
        val[j] = yn * (gv / (1.f + expf(-gv)));
        ssum += val[j];
    }
    float mean = blockReduce256(ssum, sh) * (1.f / DQ);
    float s2 = 0.f;
    #pragma unroll
    for (int j = 0; j < 4; j++) { float c = val[j] - mean; s2 += c * c; }
    float var = blockReduce256(s2, sh) * (1.f / DQ);
    float lrstd = rsqrtf(var + 1e-5f);
    float xl[4]; float sa = 0.f;
    #pragma unroll
    for (int j = 0; j < 4; j++) {
        float v = (val[j] - mean) * lrstd * ln_g[4 * DQ + d0 + j] + ln_b[4 * DQ + d0 + j];
        xl[j] = v; sa += fabsf(v);
    }
    float ma = blockReduce256(sa, sh) * (1.f / DQ);
    float clipv = fmaxf(ma, 1e-8f) * 2.5f;
    float scale = clipv / 127.f;
    __nv_bfloat16 q[4];
    #pragma unroll
    for (int j = 0; j < 4; j++)
        q[j] = __float2bfloat16(rintf(fminf(fmaxf(xl[j] / scale, -127.f), 127.f)));
    size_t off = (size_t)m * DQ + d0;
    *(__nv_bfloat162*)(g_xq5 + off)     = __nv_bfloat162(q[0], q[1]);
    *(__nv_bfloat162*)(g_xq5 + off + 2) = __nv_bfloat162(q[2], q[3]);
    if (threadIdx.x == 0) g_xscale5[m] = scale;
}

// ---------------- launcher ----------------------------------------------------
extern "C" void kernel_launch(void* const* d_in, const int* in_sizes, int n_in,
                              void* d_out, int out_size) {
    const float* x         = (const float*)d_in[0];
    const float* mu_r      = (const float*)d_in[1];
    const float* mu_k      = (const float*)d_in[2];
    const float* mu_v      = (const float*)d_in[3];
    const float* mu_g      = (const float*)d_in[4];
    const float* log_decay = (const float*)d_in[5];
    const float* u         = (const float*)d_in[6];
    const float* proj_w    = (const float*)d_in[7];
    const float* ln_g      = (const float*)d_in[8];
    const float* ln_b      = (const float*)d_in[9];
    const float* gn_g      = (const float*)d_in[10];
    const float* gn_b      = (const float*)d_in[11];
    float* out = (float*)d_out;

    wq_scale_kernel<<<5, 1024>>>(proj_w);
    wq_quant_kernel<<<5120, 256>>>(proj_w);
    lnq4_kernel<<<MROWS, 256>>>(x, mu_r, mu_k, mu_v, mu_g, ln_g, ln_b);
    gemm_kernel<<<dim3(64, 8, 4), 256>>>(nullptr);
    wkv_kernel<<<512, 256>>>(log_decay, u);
    gngate_kernel<<<MROWS, 256>>>(gn_g, gn_b, ln_g, ln_b);
    gemm_kernel<<<dim3(64, 8, 1), 256>>>(out);
}

// round 3
// speedup vs baseline: 1.3019x; 1.3019x over previous
#include <cuda_runtime.h>
#include <cuda_bf16.h>
#include <cstdint>

#define BQ 4
#define TQ 2048
#define DQ 1024
#define HQ 16
#define SQ 64
#define CQ 64
#define MROWS (BQ*TQ)   /* 8192 */

// ---------------- device scratch ----------------------------------------------
__device__ __align__(256) __nv_bfloat16 g_wq[5u*1024u*1024u];
__device__ float         g_wscale[5];
__device__ float         g_partial[5*64];
__device__ __align__(256) __nv_bfloat16 g_xq[4u*MROWS*DQ];
__device__ float         g_xscale[4*MROWS];
__device__ __align__(256) float g_r[MROWS*DQ];
__device__ __align__(256) float g_k[MROWS*DQ];
__device__ __align__(256) float g_v[MROWS*DQ];
__device__ __align__(256) float g_gate[MROWS*DQ];
__device__ __align__(256) float g_y[MROWS*DQ];
__device__ __align__(256) __nv_bfloat16 g_xq5[MROWS*DQ];
__device__ float         g_xscale5[MROWS];

// ---------------- PTX helpers --------------------------------------------------
__device__ __forceinline__ uint32_t smem_u32(const void* p) {
    uint32_t a;
    asm("{ .reg .u64 t; cvta.to.shared.u64 t, %1; cvt.u32.u64 %0, t; }" : "=r"(a) : "l"(p));
    return a;
}
__device__ __forceinline__ void cpasync16(uint32_t saddr, const void* g) {
    asm volatile("cp.async.cg.shared.global [%0], [%1], 16;" :: "r"(saddr), "l"(g) : "memory");
}
#define CP_COMMIT() asm volatile("cp.async.commit_group;" ::: "memory")

__device__ __forceinline__ void ldsm_x4(uint32_t& r0, uint32_t& r1, uint32_t& r2, uint32_t& r3,
                                        uint32_t addr) {
    asm volatile("ldmatrix.sync.aligned.m8n8.x4.shared.b16 {%0,%1,%2,%3}, [%4];"
        : "=r"(r0), "=r"(r1), "=r"(r2), "=r"(r3) : "r"(addr));
}
__device__ __forceinline__ void mma_bf16(float c[4], const uint32_t a[4], const uint32_t b[2]) {
    asm volatile(
        "mma.sync.aligned.m16n8k16.row.col.f32.bf16.bf16.f32 "
        "{%0,%1,%2,%3}, {%4,%5,%6,%7}, {%8,%9}, {%0,%1,%2,%3};\n"
        : "+f"(c[0]), "+f"(c[1]), "+f"(c[2]), "+f"(c[3])
        : "r"(a[0]), "r"(a[1]), "r"(a[2]), "r"(a[3]), "r"(b[0]), "r"(b[1]));
}

// ---------------- generic helpers ---------------------------------------------
__device__ __forceinline__ float blockReduce256(float v, float* sh) {
    #pragma unroll
    for (int o = 16; o; o >>= 1) v += __shfl_xor_sync(0xffffffffu, v, o);
    __syncthreads();
    if ((threadIdx.x & 31) == 0) sh[threadIdx.x >> 5] = v;
    __syncthreads();
    if (threadIdx.x == 0) { float s = sh[0]; for (int i = 1; i < 8; i++) s += sh[i]; sh[0] = s; }
    __syncthreads();
    return sh[0];
}

// ---------------- weight quantization -----------------------------------------
__global__ void wq_scale1_kernel(const float* __restrict__ w) {
    __shared__ float sh[8];
    int z = blockIdx.y, blk = blockIdx.x, tid = threadIdx.x;
    const float* base = w + (size_t)z * 1048576u + (size_t)blk * 16384u;
    float s = 0.f;
    #pragma unroll
    for (int j = 0; j < 16; j++) {
        float4 v = *(const float4*)(base + (tid + j * 256) * 4);
        s += fabsf(v.x) + fabsf(v.y) + fabsf(v.z) + fabsf(v.w);
    }
    #pragma unroll
    for (int o = 16; o; o >>= 1) s += __shfl_xor_sync(0xffffffffu, s, o);
    if ((tid & 31) == 0) sh[tid >> 5] = s;
    __syncthreads();
    if (tid == 0) {
        float t = 0.f;
        #pragma unroll
        for (int i = 0; i < 8; i++) t += sh[i];
        g_partial[z * 64 + blk] = t;
    }
}

__global__ void wq_scale2_kernel() {
    int warp = threadIdx.x >> 5, lane = threadIdx.x & 31;
    if (warp < 5) {
        float s = g_partial[warp * 64 + lane] + g_partial[warp * 64 + 32 + lane];
        #pragma unroll
        for (int o = 16; o; o >>= 1) s += __shfl_xor_sync(0xffffffffu, s, o);
        if (lane == 0) g_wscale[warp] = fmaxf(s * (1.f / 1048576.f), 1e-8f);
    }
}

__global__ void wq_quant_kernel(const float* __restrict__ w) {
    int idx = (blockIdx.x * 256 + threadIdx.x) * 4;
    int z = idx >> 20;
    float s = g_wscale[z];
    float4 wv = *(const float4*)(w + idx);
    float vv[4] = {wv.x, wv.y, wv.z, wv.w};
    __nv_bfloat16 q[4];
    #pragma unroll
    for (int j = 0; j < 4; j++) {
        float wn = vv[j] / s;
        wn = fminf(fmaxf(wn, -1.f), 1.f);
        q[j] = __float2bfloat16(rintf(wn));
    }
    *(__nv_bfloat162*)(g_wq + idx)     = __nv_bfloat162(q[0], q[1]);
    *(__nv_bfloat162*)(g_wq + idx + 2) = __nv_bfloat162(q[2], q[3]);
}

// ---------------- token shift + LN + act quant for r,k,v,g --------------------
__global__ void lnq4_kernel(const float* __restrict__ x,
                            const float* __restrict__ mu_r, const float* __restrict__ mu_k,
                            const float* __restrict__ mu_v, const float* __restrict__ mu_g,
                            const float* __restrict__ ln_g, const float* __restrict__ ln_b) {
    __shared__ float sh[16];
    int m = blockIdx.x;
    int d0 = threadIdx.x * 4;
    const float* xr = x + (size_t)m * DQ;
    float4 xv = *(const float4*)(xr + d0);
    float4 xsv = make_float4(0.f, 0.f, 0.f, 0.f);
    if ((m & (TQ - 1)) != 0) xsv = *(const float4*)(xr - DQ + d0);
    float xb[4] = {xv.x, xv.y, xv.z, xv.w};
    float dx[4] = {xsv.x - xv.x, xsv.y - xv.y, xsv.z - xv.z, xsv.w - xv.w};
    const float* mus[4] = {mu_r, mu_k, mu_v, mu_g};
    #pragma unroll
    for (int i = 0; i < 4; i++) {
        float4 mu = *(const float4*)(mus[i] + d0);
        float mm[4] = {mu.x, mu.y, mu.z, mu.w};
        float inp[4];
        float s = 0.f;
        #pragma unroll
        for (int j = 0; j < 4; j++) { inp[j] = fmaf(dx[j], mm[j], xb[j]); s += inp[j]; }
        float mean = blockReduce256(s, sh) * (1.f / DQ);
        float s2 = 0.f;
        #pragma unroll
        for (int j = 0; j < 4; j++) { float c = inp[j] - mean; s2 += c * c; }
        float var = blockReduce256(s2, sh) * (1.f / DQ);
        float rstd = rsqrtf(var + 1e-5f);
        float xl[4]; float sa = 0.f;
        #pragma unroll
        for (int j = 0; j < 4; j++) {
            float v = (inp[j] - mean) * rstd * ln_g[i * DQ + d0 + j] + ln_b[i * DQ + d0 + j];
            xl[j] = v; sa += fabsf(v);
        }
        float ma = blockReduce256(sa, sh) * (1.f / DQ);
        float clipv = fmaxf(ma, 1e-8f) * 2.5f;
        float scale = clipv / 127.f;
        __nv_bfloat16 q[4];
        #pragma unroll
        for (int j = 0; j < 4; j++)
            q[j] = __float2bfloat16(rintf(fminf(fmaxf(xl[j] / scale, -127.f), 127.f)));
        size_t off = (size_t)i * MROWS * DQ + (size_t)m * DQ + d0;
        *(__nv_bfloat162*)(g_xq + off)     = __nv_bfloat162(q[0], q[1]);
        *(__nv_bfloat162*)(g_xq + off + 2) = __nv_bfloat162(q[2], q[3]);
        if (threadIdx.x == 0) g_xscale[i * MROWS + m] = scale;
    }
}

// ---------------- mma.sync GEMM with ldmatrix + cp.async pipeline -------------
// CTA 128x128, BK=64, 3 stages. Warp grid 2(M)x4(N), warp tile 64x32.
#define GK_TILES 16
#define STAGE_BYTES 32768   /* A 16KB + B 16KB */

__global__ void __launch_bounds__(256) gemm_mma_kernel(float* __restrict__ out_final) {
    extern __shared__ char smem_raw[];
    uint32_t sb = (smem_u32(smem_raw) + 1023u) & ~1023u;
    int tid = threadIdx.x, warp = tid >> 5, lane = tid & 31;
    int wm = warp >> 2, wn = warp & 3;
    int gid = lane >> 2, tig = lane & 3;

    int proj = (gridDim.z > 1) ? blockIdx.z : 4;
    const __nv_bfloat16* Ag = (proj < 4) ? (g_xq + (size_t)proj * MROWS * DQ) : g_xq5;
    const __nv_bfloat16* Bg = g_wq + (size_t)proj * DQ * DQ;
    const __nv_bfloat16* Abase = Ag + (size_t)blockIdx.x * 128 * DQ;
    const __nv_bfloat16* Bbase = Bg + (size_t)blockIdx.y * 128 * DQ;

    // per-thread cp.async source/dest (512 x 16B chunks per operand per stage)
    int ldrow = tid >> 3, ldc = tid & 7;            // 4 iters: rows tid>>3 + i*32
    // ldmatrix per-thread row/col components
    int rowA = wm * 64 + (lane & 7) + ((lane >> 3) & 1) * 8;   // + mt*16
    uint32_t colA = (uint32_t)((lane >> 4) << 4);               // +ks*32
    int rowB = wn * 32 + (lane & 7) + (lane >> 4) * 8;          // + p*16
    uint32_t colB = (uint32_t)(((lane >> 3) & 1) << 4);

    float acc[4][4][4];
    #pragma unroll
    for (int a = 0; a < 4; a++)
        #pragma unroll
        for (int b = 0; b < 4; b++)
            #pragma unroll
            for (int c = 0; c < 4; c++) acc[a][b][c] = 0.f;

    auto load_stage = [&](int kt, int buf) {
        uint32_t sA = sb + buf * STAGE_BYTES;
        uint32_t sB = sA + 16384;
        int kb = kt * 64;
        #pragma unroll
        for (int i = 0; i < 4; i++) {
            int row = ldrow + i * 32;
            uint32_t off = (uint32_t)(row * 128 + ldc * 16);
            off ^= (off >> 3) & 0x70;
            const __nv_bfloat16* gp = Abase + (size_t)row * DQ + kb + ldc * 8;
            cpasync16(sA + off, gp);
            cpasync16(sB + off, Bbase + (size_t)row * DQ + kb + ldc * 8);
        }
        CP_COMMIT();
    };

    load_stage(0, 0);
    load_stage(1, 1);

    for (int kt = 0; kt < GK_TILES; kt++) {
        int buf = kt % 3;
        if (kt < GK_TILES - 1) asm volatile("cp.async.wait_group 1;" ::: "memory");
        else                   asm volatile("cp.async.wait_group 0;" ::: "memory");
        __syncthreads();
        if (kt + 2 < GK_TILES) load_stage(kt + 2, (kt + 2) % 3);

        uint32_t sA = sb + buf * STAGE_BYTES;
        uint32_t sB = sA + 16384;
        #pragma unroll
        for (int ks = 0; ks < 4; ks++) {
            uint32_t af[4][4], bf[4][2];
            #pragma unroll
            for (int mt = 0; mt < 4; mt++) {
                uint32_t off = (uint32_t)((rowA + mt * 16) * 128) + (uint32_t)(ks * 32) + colA;
                off ^= (off >> 3) & 0x70;
                ldsm_x4(af[mt][0], af[mt][1], af[mt][2], af[mt][3], sA + off);
            }
            #pragma unroll
            for (int p = 0; p < 2; p++) {
                uint32_t off = (uint32_t)((rowB + p * 16) * 128) + (uint32_t)(ks * 32) + colB;
                off ^= (off >> 3) & 0x70;
                ldsm_x4(bf[2*p][0], bf[2*p][1], bf[2*p+1][0], bf[2*p+1][1], sB + off);
            }
            #pragma unroll
            for (int mt = 0; mt < 4; mt++)
                #pragma unroll
                for (int nt = 0; nt < 4; nt++)
                    mma_bf16(acc[mt][nt], af[mt], bf[nt]);
        }
    }
    // no sync needed before epilogue: each warp's accumulators are complete.

    float sw = g_wscale[proj];
    #pragma unroll
    for (int mt = 0; mt < 4; mt++) {
        int mrow0 = blockIdx.x * 128 + wm * 64 + mt * 16 + gid;
        #pragma unroll
        for (int half = 0; half < 2; half++) {
            int mrow = mrow0 + half * 8;
            float sx = ((proj < 4) ? g_xscale[proj * MROWS + mrow] : g_xscale5[mrow]) * sw;
            #pragma unroll
            for (int nt = 0; nt < 4; nt++) {
                int ncol = blockIdx.y * 128 + wn * 32 + nt * 8 + tig * 2;
                float2 v;
                v.x = acc[mt][nt][half * 2]     * sx;
                v.y = acc[mt][nt][half * 2 + 1] * sx;
                float* dst;
                if (proj == 4)      dst = out_final + (size_t)mrow * DQ + ncol;
                else if (proj == 3) dst = g_gate + (size_t)mrow * DQ + ncol;
                else {
                    int b = mrow >> 11, t = mrow & (TQ - 1);
                    int h = ncol >> 6, s0 = ncol & 63;
                    float* basep = (proj == 0) ? g_r : (proj == 1) ? g_k : g_v;
                    dst = basep + (((size_t)(b * HQ + h) * TQ) + t) * SQ + s0;
                }
                *(float2*)dst = v;
            }
        }
    }
}

// ---------------- WKV recurrence ----------------------------------------------
__global__ void wkv_kernel(const float* __restrict__ log_decay, const float* __restrict__ uu) {
    __shared__ float rs[4096], ksm[4096], wp[4096];   // 48 KB
    int bh = blockIdx.x >> 3;
    int og = blockIdx.x & 7;
    int h = bh & (HQ - 1);
    int tid = threadIdx.x, warp = tid >> 5, lane = tid & 31;
    int o = og * 8 + warp;
    int s0 = 2 * lane;

    #pragma unroll
    for (int j = 0; j < 16; j++) {
        int e = tid + j * 256;
        int tt = e >> 6, ss = e & 63;
        float lw = -expf(log_decay[h * 64 + ss]);
        wp[e] = expf((float)(tt + 1) * lw);
    }
    __syncthreads();
    float2 w2  = *(const float2*)&wp[s0];
    float2 wC2 = *(const float2*)&wp[63 * 64 + s0];
    float2 u2  = make_float2(expf(uu[h * 64 + s0]), expf(uu[h * 64 + s0 + 1]));
    float2 S2  = make_float2(0.f, 0.f);
    size_t bhbase = (size_t)bh * TQ * SQ;

    for (int c = 0; c < TQ / CQ; c++) {
        size_t base = bhbase + (size_t)c * CQ * SQ;
        #pragma unroll
        for (int j = 0; j < 4; j++) {
            int e = tid + j * 256;
            *(float4*)&rs[e * 4]  = *(const float4*)&g_r[base + e * 4];
            *(float4*)&ksm[e * 4] = *(const float4*)&g_k[base + e * 4];
        }
        float vlo = g_v[base + (size_t)lane * SQ + o];
        float vhi = g_v[base + (size_t)(lane + 32) * SQ + o];
        __syncthreads();
        float2 Q = make_float2(0.f, 0.f), R = make_float2(0.f, 0.f), pw = make_float2(1.f, 1.f);
        for (int t = CQ - 1; t >= 0; t--) {
            float vt = __shfl_sync(0xffffffffu, (t < 32) ? vlo : vhi, t & 31);
            float2 kk  = *(const float2*)&ksm[t * 64 + s0];
            float2 rr  = *(const float2*)&rs[t * 64 + s0];
            float2 wpt = *(const float2*)&wp[t * 64 + s0];
            float kv0 = kk.x * vt, kv1 = kk.y * vt;
            Q.x = fmaf(w2.x, Q.x, kv0); Q.y = fmaf(w2.y, Q.y, kv1);
            float a0 = fmaf(u2.x, kv0, Q.x); a0 = fmaf(wpt.x, S2.x, a0);
            float a1 = fmaf(u2.y, kv1, Q.y); a1 = fmaf(wpt.y, S2.y, a1);
            float p = fmaf(rr.x, a0, rr.y * a1);
            R.x = fmaf(pw.x, kv0, R.x); R.y = fmaf(pw.y, kv1, R.y);
            pw.x *= w2.x; pw.y *= w2.y;
            #pragma unroll
            for (int off = 16; off; off >>= 1) p += __shfl_xor_sync(0xffffffffu, p, off);
            if (lane == 0) g_y[base + (size_t)t * SQ + o] = p;
        }
        S2.x = fmaf(wC2.x, S2.x, R.x); S2.y = fmaf(wC2.y, S2.y, R.y);
        __syncthreads();
    }
}

// ---------------- GroupNorm + SiLU gate + LN + quant (proj 4 input) -----------
__global__ void gngate_kernel(const float* __restrict__ gn_g, const float* __restrict__ gn_b,
                              const float* __restrict__ ln_g, const float* __restrict__ ln_b) {
    __shared__ float sh[16];
    int m = blockIdx.x;
    int b = m >> 11, t = m & (TQ - 1);
    int d0 = threadIdx.x * 4;
    int h = d0 >> 6, s = d0 & 63;
    float4 yv4 = *(const float4*)(g_y + ((size_t)(b * HQ + h) * TQ + t) * SQ + s);
    float yv[4] = {yv4.x, yv4.y, yv4.z, yv4.w};
    float gs = yv[0] + yv[1] + yv[2] + yv[3];
    #pragma unroll
    for (int off = 8; off; off >>= 1) gs += __shfl_xor_sync(0xffffffffu, gs, off);
    float gm = gs * (1.f / 64.f);
    float g2 = 0.f;
    #pragma unroll
    for (int j = 0; j < 4; j++) { float c = yv[j] - gm; g2 += c * c; }
    #pragma unroll
    for (int off = 8; off; off >>= 1) g2 += __shfl_xor_sync(0xffffffffu, g2, off);
    float rstd = rsqrtf(g2 * (1.f / 64.f) + 1e-5f);
    float4 gg4 = *(const float4*)(g_gate + (size_t)m * DQ + d0);
    float gg[4] = {gg4.x, gg4.y, gg4.z, gg4.w};
    float val[4];
    float ssum = 0.f;
    #pragma unroll
    for (int j = 0; j < 4; j++) {
        float yn = (yv[j] - gm) * rstd * gn_g[d0 + j] + gn_b[d0 + j];
        float gv = gg[j];
        val[j] = yn * (gv / (1.f + expf(-gv)));
        ssum += val[j];
    }
    float mean = blockReduce256(ssum, sh) * (1.f / DQ);
    float s2 = 0.f;
    #pragma unroll
    for (int j = 0; j < 4; j++) { float c = val[j] - mean; s2 += c * c; }
    float var = blockReduce256(s2, sh) * (1.f / DQ);
    float lrstd = rsqrtf(var + 1e-5f);
    float xl[4]; float sa = 0.f;
    #pragma unroll
    for (int j = 0; j < 4; j++) {
        float v = (val[j] - mean) * lrstd * ln_g[4 * DQ + d0 + j] + ln_b[4 * DQ + d0 + j];
        xl[j] = v; sa += fabsf(v);
    }
    float ma = blockReduce256(sa, sh) * (1.f / DQ);
    float clipv = fmaxf(ma, 1e-8f) * 2.5f;
    float scale = clipv / 127.f;
    __nv_bfloat16 q[4];
    #pragma unroll
    for (int j = 0; j < 4; j++)
        q[j] = __float2bfloat16(rintf(fminf(fmaxf(xl[j] / scale, -127.f), 127.f)));
    size_t off = (size_t)m * DQ + d0;
    *(__nv_bfloat162*)(g_xq5 + off)     = __nv_bfloat162(q[0], q[1]);
    *(__nv_bfloat162*)(g_xq5 + off + 2) = __nv_bfloat162(q[2], q[3]);
    if (threadIdx.x == 0) g_xscale5[m] = scale;
}

// ---------------- launcher ----------------------------------------------------
#define GEMM_SMEM (3 * STAGE_BYTES + 1024)

extern "C" void kernel_launch(void* const* d_in, const int* in_sizes, int n_in,
                              void* d_out, int out_size) {
    const float* x         = (const float*)d_in[0];
    const float* mu_r      = (const float*)d_in[1];
    const float* mu_k      = (const float*)d_in[2];
    const float* mu_v      = (const float*)d_in[3];
    const float* mu_g      = (const float*)d_in[4];
    const float* log_decay = (const float*)d_in[5];
    const float* u         = (const float*)d_in[6];
    const float* proj_w    = (const float*)d_in[7];
    const float* ln_g      = (const float*)d_in[8];
    const float* ln_b      = (const float*)d_in[9];
    const float* gn_g      = (const float*)d_in[10];
    const float* gn_b      = (const float*)d_in[11];
    float* out = (float*)d_out;

    cudaFuncSetAttribute(gemm_mma_kernel, cudaFuncAttributeMaxDynamicSharedMemorySize, GEMM_SMEM);

    wq_scale1_kernel<<<dim3(64, 5), 256>>>(proj_w);
    wq_scale2_kernel<<<1, 256>>>();
    wq_quant_kernel<<<5120, 256>>>(proj_w);
    lnq4_kernel<<<MROWS, 256>>>(x, mu_r, mu_k, mu_v, mu_g, ln_g, ln_b);
    gemm_mma_kernel<<<dim3(64, 8, 4), 256, GEMM_SMEM>>>(nullptr);
    wkv_kernel<<<512, 256>>>(log_decay, u);
    gngate_kernel<<<MROWS, 256>>>(gn_g, gn_b, ln_g, ln_b);
    gemm_mma_kernel<<<dim3(64, 8, 1), 256, GEMM_SMEM>>>(out);
}

// round 4
// speedup vs baseline: 1.4740x; 1.1322x over previous
#include <cuda_runtime.h>
#include <cuda_bf16.h>
#include <cstdint>

#define BQ 4
#define TQ 2048
#define DQ 1024
#define HQ 16
#define SQ 64
#define CQ 64
#define MROWS (BQ*TQ)   /* 8192 */

typedef unsigned long long ULL;

// ---------------- device scratch ----------------------------------------------
__device__ __align__(256) __nv_bfloat16 g_wq[5u*1024u*1024u];
__device__ float         g_wscale[5];
__device__ float         g_partial[5*64];
__device__ __align__(256) __nv_bfloat16 g_xq[4u*MROWS*DQ];
__device__ float         g_xscale[4*MROWS];
__device__ __align__(256) float g_r[MROWS*DQ];
__device__ __align__(256) float g_k[MROWS*DQ];
__device__ __align__(256) float g_v[MROWS*DQ];
__device__ __align__(256) float g_gate[MROWS*DQ];
__device__ __align__(256) float g_y[MROWS*DQ];
__device__ __align__(256) __nv_bfloat16 g_xq5[MROWS*DQ];
__device__ float         g_xscale5[MROWS];

// ---------------- PTX helpers --------------------------------------------------
__device__ __forceinline__ uint32_t smem_u32(const void* p) {
    uint32_t a;
    asm("{ .reg .u64 t; cvta.to.shared.u64 t, %1; cvt.u32.u64 %0, t; }" : "=r"(a) : "l"(p));
    return a;
}
__device__ __forceinline__ void cpasync16(uint32_t saddr, const void* g) {
    asm volatile("cp.async.cg.shared.global [%0], [%1], 16;" :: "r"(saddr), "l"(g) : "memory");
}
#define CP_COMMIT() asm volatile("cp.async.commit_group;" ::: "memory")

__device__ __forceinline__ void ldsm_x4(uint32_t& r0, uint32_t& r1, uint32_t& r2, uint32_t& r3,
                                        uint32_t addr) {
    asm volatile("ldmatrix.sync.aligned.m8n8.x4.shared.b16 {%0,%1,%2,%3}, [%4];"
        : "=r"(r0), "=r"(r1), "=r"(r2), "=r"(r3) : "r"(addr));
}
__device__ __forceinline__ void mma_bf16(float c[4], const uint32_t a[4], const uint32_t b[2]) {
    asm volatile(
        "mma.sync.aligned.m16n8k16.row.col.f32.bf16.bf16.f32 "
        "{%0,%1,%2,%3}, {%4,%5,%6,%7}, {%8,%9}, {%0,%1,%2,%3};\n"
        : "+f"(c[0]), "+f"(c[1]), "+f"(c[2]), "+f"(c[3])
        : "r"(a[0]), "r"(a[1]), "r"(a[2]), "r"(a[3]), "r"(b[0]), "r"(b[1]));
}

// packed f32x2 (Blackwell base ISA)
__device__ __forceinline__ ULL pk2(float a, float b) {
    ULL r; asm("mov.b64 %0, {%1, %2};" : "=l"(r) : "f"(a), "f"(b)); return r;
}
__device__ __forceinline__ void upk2(ULL v, float& a, float& b) {
    asm("mov.b64 {%0, %1}, %2;" : "=f"(a), "=f"(b) : "l"(v));
}
__device__ __forceinline__ ULL fma2(ULL a, ULL b, ULL c) {
    ULL d; asm("fma.rn.f32x2 %0, %1, %2, %3;" : "=l"(d) : "l"(a), "l"(b), "l"(c)); return d;
}
__device__ __forceinline__ ULL mul2(ULL a, ULL b) {
    ULL d; asm("mul.rn.f32x2 %0, %1, %2;" : "=l"(d) : "l"(a), "l"(b)); return d;
}

__device__ __forceinline__ float warpsum(float v) {
    #pragma unroll
    for (int o = 16; o; o >>= 1) v += __shfl_xor_sync(0xffffffffu, v, o);
    return v;
}
__device__ __forceinline__ uint32_t bf2bits(float a, float b) {
    __nv_bfloat162 h(__float2bfloat16(a), __float2bfloat16(b));
    return *(uint32_t*)&h;
}

// ---------------- weight quantization -----------------------------------------
__global__ void wq_scale1_kernel(const float* __restrict__ w) {
    __shared__ float sh[8];
    int z = blockIdx.y, blk = blockIdx.x, tid = threadIdx.x;
    const float* base = w + (size_t)z * 1048576u + (size_t)blk * 16384u;
    float s = 0.f;
    #pragma unroll
    for (int j = 0; j < 16; j++) {
        float4 v = *(const float4*)(base + (tid + j * 256) * 4);
        s += fabsf(v.x) + fabsf(v.y) + fabsf(v.z) + fabsf(v.w);
    }
    s = warpsum(s);
    if ((tid & 31) == 0) sh[tid >> 5] = s;
    __syncthreads();
    if (tid == 0) {
        float t = 0.f;
        #pragma unroll
        for (int i = 0; i < 8; i++) t += sh[i];
        g_partial[z * 64 + blk] = t;
    }
}

__global__ void wq_scale2_kernel() {
    int warp = threadIdx.x >> 5, lane = threadIdx.x & 31;
    if (warp < 5) {
        float s = g_partial[warp * 64 + lane] + g_partial[warp * 64 + 32 + lane];
        s = warpsum(s);
        if (lane == 0) g_wscale[warp] = fmaxf(s * (1.f / 1048576.f), 1e-8f);
    }
}

__global__ void wq_quant_kernel(const float* __restrict__ w) {
    int idx = (blockIdx.x * 256 + threadIdx.x) * 4;
    int z = idx >> 20;
    float s = g_wscale[z];
    float4 wv = *(const float4*)(w + idx);
    float vv[4] = {wv.x, wv.y, wv.z, wv.w};
    __nv_bfloat16 q[4];
    #pragma unroll
    for (int j = 0; j < 4; j++) {
        float wn = vv[j] / s;
        wn = fminf(fmaxf(wn, -1.f), 1.f);
        q[j] = __float2bfloat16(rintf(wn));
    }
    *(__nv_bfloat162*)(g_wq + idx)     = __nv_bfloat162(q[0], q[1]);
    *(__nv_bfloat162*)(g_wq + idx + 2) = __nv_bfloat162(q[2], q[3]);
}

// ---------------- token shift + LN + act quant (warp-per-row) -----------------
__global__ void __launch_bounds__(256) lnq4_kernel(
        const float* __restrict__ x,
        const float* __restrict__ mu_r, const float* __restrict__ mu_k,
        const float* __restrict__ mu_v, const float* __restrict__ mu_g,
        const float* __restrict__ ln_g, const float* __restrict__ ln_b) {
    int warp = threadIdx.x >> 5, lane = threadIdx.x & 31;
    int m = blockIdx.x * 8 + warp;
    int d0 = lane * 32;
    const float* xr = x + (size_t)m * DQ + d0;

    float xv[32], dx[32];
    #pragma unroll
    for (int j = 0; j < 8; j++) {
        float4 a = *(const float4*)(xr + j * 4);
        xv[j*4+0] = a.x; xv[j*4+1] = a.y; xv[j*4+2] = a.z; xv[j*4+3] = a.w;
    }
    if ((m & (TQ - 1)) != 0) {
        #pragma unroll
        for (int j = 0; j < 8; j++) {
            float4 a = *(const float4*)(xr - DQ + j * 4);
            dx[j*4+0] = a.x - xv[j*4+0]; dx[j*4+1] = a.y - xv[j*4+1];
            dx[j*4+2] = a.z - xv[j*4+2]; dx[j*4+3] = a.w - xv[j*4+3];
        }
    } else {
        #pragma unroll
        for (int j = 0; j < 32; j++) dx[j] = -xv[j];
    }

    const float* mus[4] = {mu_r, mu_k, mu_v, mu_g};
    #pragma unroll 1
    for (int i = 0; i < 4; i++) {
        float inp[32];
        float s = 0.f;
        const float* mup = mus[i] + d0;
        #pragma unroll
        for (int j = 0; j < 8; j++) {
            float4 mu = *(const float4*)(mup + j * 4);
            inp[j*4+0] = fmaf(dx[j*4+0], mu.x, xv[j*4+0]);
            inp[j*4+1] = fmaf(dx[j*4+1], mu.y, xv[j*4+1]);
            inp[j*4+2] = fmaf(dx[j*4+2], mu.z, xv[j*4+2]);
            inp[j*4+3] = fmaf(dx[j*4+3], mu.w, xv[j*4+3]);
            s += inp[j*4+0] + inp[j*4+1] + inp[j*4+2] + inp[j*4+3];
        }
        float mean = warpsum(s) * (1.f / DQ);
        float s2 = 0.f;
        #pragma unroll
        for (int j = 0; j < 32; j++) { float c = inp[j] - mean; s2 += c * c; }
        float rstd = rsqrtf(warpsum(s2) * (1.f / DQ) + 1e-5f);
        const float* gp = ln_g + i * DQ + d0;
        const float* bp = ln_b + i * DQ + d0;
        float sa = 0.f;
        #pragma unroll
        for (int j = 0; j < 8; j++) {
            float4 gg = *(const float4*)(gp + j * 4);
            float4 bb = *(const float4*)(bp + j * 4);
            float v0 = (inp[j*4+0] - mean) * rstd * gg.x + bb.x;
            float v1 = (inp[j*4+1] - mean) * rstd * gg.y + bb.y;
            float v2 = (inp[j*4+2] - mean) * rstd * gg.z + bb.z;
            float v3 = (inp[j*4+3] - mean) * rstd * gg.w + bb.w;
            inp[j*4+0] = v0; inp[j*4+1] = v1; inp[j*4+2] = v2; inp[j*4+3] = v3;
            sa += fabsf(v0) + fabsf(v1) + fabsf(v2) + fabsf(v3);
        }
        float ma = warpsum(sa) * (1.f / DQ);
        float scale = fmaxf(ma, 1e-8f) * 2.5f / 127.f;
        float inv = 1.f / scale;
        size_t off = (size_t)i * MROWS * DQ + (size_t)m * DQ + d0;
        #pragma unroll
        for (int g = 0; g < 4; g++) {
            uint4 u;
            float q[8];
            #pragma unroll
            for (int j = 0; j < 8; j++)
                q[j] = rintf(fminf(fmaxf(inp[g*8+j] * inv, -127.f), 127.f));
            u.x = bf2bits(q[0], q[1]); u.y = bf2bits(q[2], q[3]);
            u.z = bf2bits(q[4], q[5]); u.w = bf2bits(q[6], q[7]);
            *(uint4*)(g_xq + off + g * 8) = u;
        }
        if (lane == 0) g_xscale[i * MROWS + m] = scale;
    }
}

// ---------------- mma.sync GEMM with ldmatrix + cp.async pipeline -------------
#define GK_TILES 16
#define STAGE_BYTES 32768   /* A 16KB + B 16KB */

__global__ void __launch_bounds__(256) gemm_mma_kernel(float* __restrict__ out_final) {
    extern __shared__ char smem_raw[];
    uint32_t sb = (smem_u32(smem_raw) + 1023u) & ~1023u;
    int tid = threadIdx.x, warp = tid >> 5, lane = tid & 31;
    int wm = warp >> 2, wn = warp & 3;
    int gid = lane >> 2, tig = lane & 3;

    int proj = (gridDim.z > 1) ? blockIdx.z : 4;
    const __nv_bfloat16* Ag = (proj < 4) ? (g_xq + (size_t)proj * MROWS * DQ) : g_xq5;
    const __nv_bfloat16* Bg = g_wq + (size_t)proj * DQ * DQ;
    const __nv_bfloat16* Abase = Ag + (size_t)blockIdx.x * 128 * DQ;
    const __nv_bfloat16* Bbase = Bg + (size_t)blockIdx.y * 128 * DQ;

    int ldrow = tid >> 3, ldc = tid & 7;
    int rowA = wm * 64 + (lane & 7) + ((lane >> 3) & 1) * 8;
    uint32_t colA = (uint32_t)((lane >> 4) << 4);
    int rowB = wn * 32 + (lane & 7) + (lane >> 4) * 8;
    uint32_t colB = (uint32_t)(((lane >> 3) & 1) << 4);

    float acc[4][4][4];
    #pragma unroll
    for (int a = 0; a < 4; a++)
        #pragma unroll
        for (int b = 0; b < 4; b++)
            #pragma unroll
            for (int c = 0; c < 4; c++) acc[a][b][c] = 0.f;

    auto load_stage = [&](int kt, int buf) {
        uint32_t sA = sb + buf * STAGE_BYTES;
        uint32_t sB = sA + 16384;
        int kb = kt * 64;
        #pragma unroll
        for (int i = 0; i < 4; i++) {
            int row = ldrow + i * 32;
            uint32_t off = (uint32_t)(row * 128 + ldc * 16);
            off ^= (off >> 3) & 0x70;
            cpasync16(sA + off, Abase + (size_t)row * DQ + kb + ldc * 8);
            cpasync16(sB + off, Bbase + (size_t)row * DQ + kb + ldc * 8);
        }
        CP_COMMIT();
    };

    load_stage(0, 0);
    load_stage(1, 1);

    for (int kt = 0; kt < GK_TILES; kt++) {
        int buf = kt % 3;
        if (kt < GK_TILES - 1) asm volatile("cp.async.wait_group 1;" ::: "memory");
        else                   asm volatile("cp.async.wait_group 0;" ::: "memory");
        __syncthreads();
        if (kt + 2 < GK_TILES) load_stage(kt + 2, (kt + 2) % 3);

        uint32_t sA = sb + buf * STAGE_BYTES;
        uint32_t sB = sA + 16384;
        #pragma unroll
        for (int ks = 0; ks < 4; ks++) {
            uint32_t af[4][4], bf[4][2];
            #pragma unroll
            for (int mt = 0; mt < 4; mt++) {
                uint32_t off = (uint32_t)((rowA + mt * 16) * 128) + (uint32_t)(ks * 32) + colA;
                off ^= (off >> 3) & 0x70;
                ldsm_x4(af[mt][0], af[mt][1], af[mt][2], af[mt][3], sA + off);
            }
            #pragma unroll
            for (int p = 0; p < 2; p++) {
                uint32_t off = (uint32_t)((rowB + p * 16) * 128) + (uint32_t)(ks * 32) + colB;
                off ^= (off >> 3) & 0x70;
                ldsm_x4(bf[2*p][0], bf[2*p][1], bf[2*p+1][0], bf[2*p+1][1], sB + off);
            }
            #pragma unroll
            for (int mt = 0; mt < 4; mt++)
                #pragma unroll
                for (int nt = 0; nt < 4; nt++)
                    mma_bf16(acc[mt][nt], af[mt], bf[nt]);
        }
    }

    float sw = g_wscale[proj];
    #pragma unroll
    for (int mt = 0; mt < 4; mt++) {
        int mrow0 = blockIdx.x * 128 + wm * 64 + mt * 16 + gid;
        #pragma unroll
        for (int half = 0; half < 2; half++) {
            int mrow = mrow0 + half * 8;
            float sx = ((proj < 4) ? g_xscale[proj * MROWS + mrow] : g_xscale5[mrow]) * sw;
            #pragma unroll
            for (int nt = 0; nt < 4; nt++) {
                int ncol = blockIdx.y * 128 + wn * 32 + nt * 8 + tig * 2;
                float2 v;
                v.x = acc[mt][nt][half * 2]     * sx;
                v.y = acc[mt][nt][half * 2 + 1] * sx;
                float* dst;
                if (proj == 4)      dst = out_final + (size_t)mrow * DQ + ncol;
                else if (proj == 3) dst = g_gate + (size_t)mrow * DQ + ncol;
                else {
                    int b = mrow >> 11, t = mrow & (TQ - 1);
                    int h = ncol >> 6, s0 = ncol & 63;
                    float* basep = (proj == 0) ? g_r : (proj == 1) ? g_k : g_v;
                    dst = basep + (((size_t)(b * HQ + h) * TQ) + t) * SQ + s0;
                }
                *(float2*)dst = v;
            }
        }
    }
}

// ---------------- WKV recurrence (2 outputs/warp, packed f32x2) ----------------
// grid 256 = 64 bh x 4 og ; block 256 = 8 warps = 16 output cols
__global__ void __launch_bounds__(256) wkv_kernel(
        const float* __restrict__ log_decay, const float* __restrict__ uu) {
    extern __shared__ float sm[];
    float* rs  = sm;            // 4096
    float* ksm = sm + 4096;     // 4096
    float* wp  = sm + 8192;     // 4096
    float* vsm = sm + 12288;    // 1024
    int bh = blockIdx.x >> 2, og = blockIdx.x & 3, h = bh & (HQ - 1);
    int tid = threadIdx.x, warp = tid >> 5, lane = tid & 31;
    int half = lane >> 4, sl = lane & 15;
    int olocal = warp * 2 + half;
    int o = og * 16 + olocal;
    int sb = sl * 4;

    #pragma unroll
    for (int j = 0; j < 16; j++) {
        int e = tid + j * 256;
        int tt = e >> 6, ss = e & 63;
        wp[e] = expf((float)(tt + 1) * (-expf(log_decay[h * 64 + ss])));
    }
    __syncthreads();

    ULL w01  = pk2(wp[sb], wp[sb + 1]),        w23  = pk2(wp[sb + 2], wp[sb + 3]);
    ULL wC01 = pk2(wp[63*64 + sb], wp[63*64 + sb + 1]);
    ULL wC23 = pk2(wp[63*64 + sb + 2], wp[63*64 + sb + 3]);
    ULL u01  = pk2(expf(uu[h*64 + sb]),     expf(uu[h*64 + sb + 1]));
    ULL u23  = pk2(expf(uu[h*64 + sb + 2]), expf(uu[h*64 + sb + 3]));
    ULL one2 = pk2(1.f, 1.f);
    ULL S01 = 0ull, S23 = 0ull;
    size_t bhb = (size_t)bh * TQ * SQ;

    int vrow = tid >> 2, vcol = (tid & 3) * 4;

    for (int c = 0; c < TQ / CQ; c++) {
        size_t base = bhb + (size_t)c * CQ * SQ;
        #pragma unroll
        for (int j = 0; j < 4; j++) {
            int e = tid + j * 256;
            *(float4*)&rs[e * 4]  = *(const float4*)&g_r[base + e * 4];
            *(float4*)&ksm[e * 4] = *(const float4*)&g_k[base + e * 4];
        }
        *(float4*)&vsm[vrow * 16 + vcol] =
            *(const float4*)&g_v[base + (size_t)vrow * SQ + og * 16 + vcol];
        __syncthreads();

        ULL Q01 = 0ull, Q23 = 0ull, R01 = 0ull, R23 = 0ull;
        ULL pw01 = one2, pw23 = one2;
        #pragma unroll 4
        for (int t = CQ - 1; t >= 0; t--) {
            float vt = vsm[t * 16 + olocal];
            ULL vtt = pk2(vt, vt);
            ulonglong2 kk  = *(const ulonglong2*)(ksm + t * 64 + sb);
            ulonglong2 rr  = *(const ulonglong2*)(rs  + t * 64 + sb);
            ulonglong2 wpt = *(const ulonglong2*)(wp  + t * 64 + sb);
            ULL kv01 = mul2(kk.x, vtt), kv23 = mul2(kk.y, vtt);
            Q01 = fma2(w01, Q01, kv01); Q23 = fma2(w23, Q23, kv23);
            ULL a01 = fma2(u01, kv01, Q01); a01 = fma2(wpt.x, S01, a01);
            ULL a23 = fma2(u23, kv23, Q23); a23 = fma2(wpt.y, S23, a23);
            ULL p2 = mul2(rr.x, a01); p2 = fma2(rr.y, a23, p2);
            float pl, ph; upk2(p2, pl, ph);
            float p = pl + ph;
            R01 = fma2(pw01, kv01, R01); R23 = fma2(pw23, kv23, R23);
            pw01 = mul2(pw01, w01); pw23 = mul2(pw23, w23);
            #pragma unroll
            for (int off = 8; off; off >>= 1) p += __shfl_xor_sync(0xffffffffu, p, off);
            if (sl == 0) g_y[base + (size_t)t * SQ + o] = p;
        }
        S01 = fma2(wC01, S01, R01); S23 = fma2(wC23, S23, R23);
        __syncthreads();
    }
}

// ---------------- GroupNorm + SiLU gate + LN + quant (warp-per-row) -----------
__global__ void __launch_bounds__(256) gngate_kernel(
        const float* __restrict__ gn_g, const float* __restrict__ gn_b,
        const float* __restrict__ ln_g, const float* __restrict__ ln_b) {
    int warp = threadIdx.x >> 5, lane = threadIdx.x & 31;
    int m = blockIdx.x * 8 + warp;
    int b = m >> 11, t = m & (TQ - 1);
    int h = lane >> 1, s0 = (lane & 1) * 32;
    int d0 = lane * 32;

    float yv[32];
    const float* yp = g_y + ((size_t)(b * HQ + h) * TQ + t) * SQ + s0;
    #pragma unroll
    for (int j = 0; j < 8; j++) {
        float4 a = *(const float4*)(yp + j * 4);
        yv[j*4+0] = a.x; yv[j*4+1] = a.y; yv[j*4+2] = a.z; yv[j*4+3] = a.w;
    }
    float gs = 0.f;
    #pragma unroll
    for (int j = 0; j < 32; j++) gs += yv[j];
    gs += __shfl_xor_sync(0xffffffffu, gs, 1);
    float gm = gs * (1.f / 64.f);
    float g2 = 0.f;
    #pragma unroll
    for (int j = 0; j < 32; j++) { float c = yv[j] - gm; g2 += c * c; }
    g2 += __shfl_xor_sync(0xffffffffu, g2, 1);
    float rstd = rsqrtf(g2 * (1.f / 64.f) + 1e-5f);

    float val[32];
    const float* gp = g_gate + (size_t)m * DQ + d0;
    float ssum = 0.f;
    #pragma unroll
    for (int j = 0; j < 8; j++) {
        float4 gg = *(const float4*)(gp + j * 4);
        float4 gn4 = *(const float4*)(gn_g + d0 + j * 4);
        float4 gb4 = *(const float4*)(gn_b + d0 + j * 4);
        float gv[4] = {gg.x, gg.y, gg.z, gg.w};
        float ga[4] = {gn4.x, gn4.y, gn4.z, gn4.w};
        float gbv[4] = {gb4.x, gb4.y, gb4.z, gb4.w};
        #pragma unroll
        for (int q = 0; q < 4; q++) {
            float yn = (yv[j*4+q] - gm) * rstd * ga[q] + gbv[q];
            float v = yn * (gv[q] / (1.f + expf(-gv[q])));
            val[j*4+q] = v; ssum += v;
        }
    }
    float mean = warpsum(ssum) * (1.f / DQ);
    float s2 = 0.f;
    #pragma unroll
    for (int j = 0; j < 32; j++) { float c = val[j] - mean; s2 += c * c; }
    float lrstd = rsqrtf(warpsum(s2) * (1.f / DQ) + 1e-5f);
    const float* lgp = ln_g + 4 * DQ + d0;
    const float* lbp = ln_b + 4 * DQ + d0;
    float sa = 0.f;
    #pragma unroll
    for (int j = 0; j < 8; j++) {
        float4 lg = *(const float4*)(lgp + j * 4);
        float4 lb = *(const float4*)(lbp + j * 4);
        float v0 = (val[j*4+0] - mean) * lrstd * lg.x + lb.x;
        float v1 = (val[j*4+1] - mean) * lrstd * lg.y + lb.y;
        float v2 = (val[j*4+2] - mean) * lrstd * lg.z + lb.z;
        float v3 = (val[j*4+3] - mean) * lrstd * lg.w + lb.w;
        val[j*4+0] = v0; val[j*4+1] = v1; val[j*4+2] = v2; val[j*4+3] = v3;
        sa += fabsf(v0) + fabsf(v1) + fabsf(v2) + fabsf(v3);
    }
    float ma = warpsum(sa) * (1.f / DQ);
    float scale = fmaxf(ma, 1e-8f) * 2.5f / 127.f;
    float inv = 1.f / scale;
    size_t off = (size_t)m * DQ + d0;
    #pragma unroll
    for (int g = 0; g < 4; g++) {
        uint4 u;
        float q[8];
        #pragma unroll
        for (int j = 0; j < 8; j++)
            q[j] = rintf(fminf(fmaxf(val[g*8+j] * inv, -127.f), 127.f));
        u.x = bf2bits(q[0], q[1]); u.y = bf2bits(q[2], q[3]);
        u.z = bf2bits(q[4], q[5]); u.w = bf2bits(q[6], q[7]);
        *(uint4*)(g_xq5 + off + g * 8) = u;
    }
    if (lane == 0) g_xscale5[m] = scale;
}

// ---------------- launcher ----------------------------------------------------
#define GEMM_SMEM (3 * STAGE_BYTES + 1024)
#define WKV_SMEM  (13312 * 4)

extern "C" void kernel_launch(void* const* d_in, const int* in_sizes, int n_in,
                              void* d_out, int out_size) {
    const float* x         = (const float*)d_in[0];
    const float* mu_r      = (const float*)d_in[1];
    const float* mu_k      = (const float*)d_in[2];
    const float* mu_v      = (const float*)d_in[3];
    const float* mu_g      = (const float*)d_in[4];
    const float* log_decay = (const float*)d_in[5];
    const float* u         = (const float*)d_in[6];
    const float* proj_w    = (const float*)d_in[7];
    const float* ln_g      = (const float*)d_in[8];
    const float* ln_b      = (const float*)d_in[9];
    const float* gn_g      = (const float*)d_in[10];
    const float* gn_b      = (const float*)d_in[11];
    float* out = (float*)d_out;

    cudaFuncSetAttribute(gemm_mma_kernel, cudaFuncAttributeMaxDynamicSharedMemorySize, GEMM_SMEM);
    cudaFuncSetAttribute(wkv_kernel, cudaFuncAttributeMaxDynamicSharedMemorySize, WKV_SMEM);

    wq_scale1_kernel<<<dim3(64, 5), 256>>>(proj_w);
    wq_scale2_kernel<<<1, 256>>>();
    wq_quant_kernel<<<5120, 256>>>(proj_w);
    lnq4_kernel<<<1024, 256>>>(x, mu_r, mu_k, mu_v, mu_g, ln_g, ln_b);
    gemm_mma_kernel<<<dim3(64, 8, 4), 256, GEMM_SMEM>>>(nullptr);
    wkv_kernel<<<256, 256, WKV_SMEM>>>(log_decay, u);
    gngate_kernel<<<1024, 256>>>(gn_g, gn_b, ln_g, ln_b);
    gemm_mma_kernel<<<dim3(64, 8, 1), 256, GEMM_SMEM>>>(out);
}